// round 9
// baseline (speedup 1.0000x reference)
#include <cuda_runtime.h>
#include <cuda_bf16.h>
#include <cuda_fp16.h>
#include <cstdint>

#define NN 40000
#define EE 640000
#define DD 128
#define LN_EPS 1e-5f
#define SCAN_BLKS 157   // ceil(40000/256)

// ================= device scratch =================
__device__ unsigned long long g_deg[NN];          // packed cnt<<44 | fx24
__device__ __align__(16) float g_dinv[NN];
__device__ int   g_rowptr[NN + 1];
__device__ int   g_part[SCAN_BLKS];
__device__ int   g_slot[EE];                      // per-edge slot within row
__device__ __align__(16) uint2 g_cv[EE];          // packed {col, val bits}
__device__ __align__(16) uint2 g_xh[(size_t)NN * 32];   // x fp16
__device__ __align__(16) uint2 g_t1h[(size_t)NN * 32];  // T1 fp16
__device__ __align__(16) uint2 g_t2h[(size_t)NN * 32];  // T2 fp16
__device__ int   g_tile_ctr;

// ================= K1: fused convert(x->fp16) + degree + slot =============
__global__ void convert_degree_kernel(const float* __restrict__ x,
                                      const int* __restrict__ ei,
                                      const float* __restrict__ w) {
    int i = blockIdx.x * blockDim.x + threadIdx.x;
    if (i < NN * 32) {
        float4 v = ((const float4*)x)[i];
        __half2 a = __floats2half2_rn(v.x, v.y);
        __half2 b = __floats2half2_rn(v.z, v.w);
        uint2 u;
        u.x = *reinterpret_cast<uint32_t*>(&a);
        u.y = *reinterpret_cast<uint32_t*>(&b);
        g_xh[i] = u;
    }
    if (i < EE) {
        int r = ei[i];
        if ((unsigned)r < NN) {
            unsigned long long fx =
                (unsigned long long)(w[i] * 16777216.0f);   // w * 2^24
            unsigned long long old =
                atomicAdd(&g_deg[r], (1ull << 44) | fx);
            g_slot[i] = (int)(old >> 44);
        }
    }
}

// ================= K2a: per-block count sums =================
__global__ void scan_reduce_kernel() {
    int i = blockIdx.x * 256 + threadIdx.x;
    int v = (i < NN) ? (int)(g_deg[i] >> 44) : 0;
    #pragma unroll
    for (int o = 16; o; o >>= 1) v += __shfl_xor_sync(0xffffffffu, v, o);
    __shared__ int ws[8];
    if ((threadIdx.x & 31) == 0) ws[threadIdx.x >> 5] = v;
    __syncthreads();
    if (threadIdx.x == 0) {
        int s = 0;
        #pragma unroll
        for (int k = 0; k < 8; k++) s += ws[k];
        g_part[blockIdx.x] = s;
    }
}

// ===== K2b: apply scan (each block scans partials locally), dinv, reset ====
__global__ void scan_apply_kernel() {
    __shared__ int pbuf[SCAN_BLKS];
    __shared__ int s_base;
    __shared__ int ws[8];
    int tid = threadIdx.x;
    if (tid < SCAN_BLKS) pbuf[tid] = g_part[tid];
    __syncthreads();
    if (tid == 0) {
        int run = 0;
        #pragma unroll 1
        for (int k = 0; k < SCAN_BLKS; k++) {
            int t = pbuf[k];
            if (k == blockIdx.x) { s_base = run; break; }
            run += t;
        }
    }

    int i = blockIdx.x * 256 + tid;
    int lane = tid & 31, wid = tid >> 5;
    unsigned long long pk = (i < NN) ? g_deg[i] : 0ull;
    int v = (int)(pk >> 44);
    int s = v;
    #pragma unroll
    for (int o = 1; o < 32; o <<= 1) {
        int t = __shfl_up_sync(0xffffffffu, s, o);
        if (lane >= o) s += t;
    }
    if (lane == 31) ws[wid] = s;
    __syncthreads();
    if (wid == 0 && lane < 8) {
        int t = ws[lane];
        #pragma unroll
        for (int o = 1; o < 8; o <<= 1) {
            int u = __shfl_up_sync(0xffu, t, o);
            if (lane >= o) t += u;
        }
        ws[lane] = t;
    }
    __syncthreads();
    int excl = s - v + (wid ? ws[wid - 1] : 0) + s_base;
    if (i < NN) {
        g_rowptr[i] = excl;
        float dg = (float)(pk & ((1ull << 44) - 1)) * 5.9604644775390625e-8f;
        g_dinv[i] = (dg > 0.f) ? rsqrtf(dg) : 0.f;
        g_deg[i] = 0ull;            // ready for next replay
    }
    if (i == 0) {
        g_tile_ctr = 0;
        g_rowptr[NN] = EE;
    }
}

// ================= K3: scatter (no atomics) =================
__global__ void scatter_kernel(const int* __restrict__ ei,
                               const float* __restrict__ w) {
    int e = blockIdx.x * blockDim.x + threadIdx.x;
    if (e >= EE) return;
    int r = ei[e];
    int c = ei[EE + e];
    if ((unsigned)r >= NN || (unsigned)c >= NN) return;
    int pos = g_rowptr[r] + g_slot[e];
    float val = -g_dinv[r] * w[e] * g_dinv[c];
    uint2 cv;
    cv.x = (uint32_t)c;
    cv.y = __float_as_uint(val);
    g_cv[pos] = cv;
}

// ================= K4/K5: SpMM fp16 in / fp16 out (unroll 2) ===============
__global__ void spmm_kernel(const uint2* __restrict__ Xh,
                            uint2* __restrict__ Yh,
                            const uint2* __restrict__ XsubH,
                            float alpha) {
    int gw = (blockIdx.x * blockDim.x + threadIdx.x) >> 5;
    if (gw >= NN) return;
    int lane = threadIdx.x & 31;
    int s = g_rowptr[gw], e2 = g_rowptr[gw + 1];
    float4 acc = make_float4(0.f, 0.f, 0.f, 0.f);
    int j = s;
    for (; j + 1 < e2; j += 2) {
        uint2 cv0 = g_cv[j], cv1 = g_cv[j + 1];
        uint2 h0 = Xh[(size_t)cv0.x * 32 + lane];
        uint2 h1 = Xh[(size_t)cv1.x * 32 + lane];
        float v0 = __uint_as_float(cv0.y), v1 = __uint_as_float(cv1.y);
        float2 a0 = __half22float2(*reinterpret_cast<__half2*>(&h0.x));
        float2 b0 = __half22float2(*reinterpret_cast<__half2*>(&h0.y));
        float2 a1 = __half22float2(*reinterpret_cast<__half2*>(&h1.x));
        float2 b1 = __half22float2(*reinterpret_cast<__half2*>(&h1.y));
        acc.x += v0 * a0.x; acc.y += v0 * a0.y; acc.z += v0 * b0.x; acc.w += v0 * b0.y;
        acc.x += v1 * a1.x; acc.y += v1 * a1.y; acc.z += v1 * b1.x; acc.w += v1 * b1.y;
    }
    if (j < e2) {
        uint2 cv0 = g_cv[j];
        uint2 h0 = Xh[(size_t)cv0.x * 32 + lane];
        float v0 = __uint_as_float(cv0.y);
        float2 a0 = __half22float2(*reinterpret_cast<__half2*>(&h0.x));
        float2 b0 = __half22float2(*reinterpret_cast<__half2*>(&h0.y));
        acc.x += v0 * a0.x; acc.y += v0 * a0.y; acc.z += v0 * b0.x; acc.w += v0 * b0.y;
    }
    float4 o;
    if (XsubH) {
        uint2 xs = XsubH[(size_t)gw * 32 + lane];
        float2 xa = __half22float2(*reinterpret_cast<__half2*>(&xs.x));
        float2 xb = __half22float2(*reinterpret_cast<__half2*>(&xs.y));
        o.x = alpha * acc.x - xa.x;
        o.y = alpha * acc.y - xa.y;
        o.z = alpha * acc.z - xb.x;
        o.w = alpha * acc.w - xb.y;
    } else {
        o.x = alpha * acc.x; o.y = alpha * acc.y;
        o.z = alpha * acc.z; o.w = alpha * acc.w;
    }
    __half2 ha = __floats2half2_rn(o.x, o.y);
    __half2 hb = __floats2half2_rn(o.z, o.w);
    uint2 u;
    u.x = *reinterpret_cast<uint32_t*>(&ha);
    u.y = *reinterpret_cast<uint32_t*>(&hb);
    Yh[(size_t)gw * 32 + lane] = u;
}

// ================= K6: fp16 mma GEMM + bias + LN + ReLU =================
#define NT 313
#define KPAD 136
#define MAT_BYTES (128 * KPAD * 2)
#define OFF_BIAS  (3 * MAT_BYTES)
#define OFF_GAMMA (OFF_BIAS + 512)
#define OFF_BETA  (OFF_GAMMA + 512)
#define GEMM_SMEM (OFF_BETA + 512)      // 105984 (x2 CTAs)

__device__ __forceinline__ void mma_f16(float* c, const uint32_t* a,
                                        uint32_t b0, uint32_t b1) {
    asm volatile(
        "mma.sync.aligned.m16n8k16.row.col.f32.f16.f16.f32 "
        "{%0,%1,%2,%3}, {%4,%5,%6,%7}, {%8,%9}, {%0,%1,%2,%3};"
        : "+f"(c[0]), "+f"(c[1]), "+f"(c[2]), "+f"(c[3])
        : "r"(a[0]), "r"(a[1]), "r"(a[2]), "r"(a[3]), "r"(b0), "r"(b1));
}

__device__ __forceinline__ void split2h(float x, float y,
                                        uint32_t& hi, uint32_t& lo) {
    __half hx = __float2half_rn(x);
    __half hy = __float2half_rn(y);
    float lx = x - __half2float(hx);
    float ly = y - __half2float(hy);
    __half2 h = __halves2half2(hx, hy);
    __half2 l = __halves2half2(__float2half_rn(lx), __float2half_rn(ly));
    hi = *reinterpret_cast<uint32_t*>(&h);
    lo = *reinterpret_cast<uint32_t*>(&l);
}

__global__ __launch_bounds__(256, 2)
void gemm_mma_kernel(const float* __restrict__ X0,
                     const char* __restrict__ X1,     // fp16 rows, 256B/row
                     const char* __restrict__ X2,     // fp16 rows
                     const float* __restrict__ W,
                     const float* __restrict__ bias,
                     const float* __restrict__ gamma,
                     const float* __restrict__ beta,
                     float* __restrict__ out) {
    extern __shared__ char smem[];
    __shared__ int s_tile;
    int tid = threadIdx.x;
    int wid = tid >> 5, lane = tid & 31;
    int tig = lane & 3, gid = lane >> 2;

    float* sBias  = (float*)(smem + OFF_BIAS);
    float* sGamma = (float*)(smem + OFF_GAMMA);
    float* sBeta  = (float*)(smem + OFF_BETA);
    if (tid < 128) {
        sBias[tid]  = bias[tid];
        sGamma[tid] = gamma[tid];
        sBeta[tid]  = beta[tid];
    }

    for (int idx = tid; idx < 3 * 16384; idx += 256) {
        int p = idx >> 14;
        int r = idx & 16383;
        int k = r >> 7, n = r & 127;
        *(__half*)(smem + p * MAT_BYTES + ((size_t)n * KPAD + k) * 2) =
            __float2half_rn(W[idx]);
    }
    __syncthreads();

    for (;;) {
        if (tid == 0) s_tile = atomicAdd(&g_tile_ctr, 1);
        __syncthreads();
        int tile = s_tile;
        if (tile >= NT) break;
        int row0 = tile * 128;

        int r0 = row0 + wid * 16 + gid;
        bool v0 = r0 < NN, v1 = (r0 + 8) < NN;

        float cacc[16][4];
        #pragma unroll
        for (int nt = 0; nt < 16; nt++)
            #pragma unroll
            for (int j = 0; j < 4; j++) cacc[nt][j] = 0.f;

        const char* mw0 = smem;
        const char* mw1 = smem + MAT_BYTES;
        const char* mw2 = smem + 2 * MAT_BYTES;

        #pragma unroll 1
        for (int ks = 0; ks < 8; ks++) {
            int k0 = ks * 16 + tig * 2;
            float2 z = make_float2(0.f, 0.f);
            float2 a00 = v0 ? *(const float2*)(X0 + (size_t)r0 * 128 + k0) : z;
            float2 a10 = v1 ? *(const float2*)(X0 + (size_t)(r0 + 8) * 128 + k0) : z;
            float2 a01 = v0 ? *(const float2*)(X0 + (size_t)r0 * 128 + k0 + 8) : z;
            float2 a11 = v1 ? *(const float2*)(X0 + (size_t)(r0 + 8) * 128 + k0 + 8) : z;
            uint32_t ahi[4], alo[4];
            split2h(a00.x, a00.y, ahi[0], alo[0]);
            split2h(a10.x, a10.y, ahi[1], alo[1]);
            split2h(a01.x, a01.y, ahi[2], alo[2]);
            split2h(a11.x, a11.y, ahi[3], alo[3]);
            uint32_t a1[4], a2[4];
            size_t o0 = (size_t)r0 * 256 + k0 * 2;
            size_t o1 = (size_t)(r0 + 8) * 256 + k0 * 2;
            a1[0] = v0 ? *(const uint32_t*)(X1 + o0) : 0u;
            a1[1] = v1 ? *(const uint32_t*)(X1 + o1) : 0u;
            a1[2] = v0 ? *(const uint32_t*)(X1 + o0 + 16) : 0u;
            a1[3] = v1 ? *(const uint32_t*)(X1 + o1 + 16) : 0u;
            a2[0] = v0 ? *(const uint32_t*)(X2 + o0) : 0u;
            a2[1] = v1 ? *(const uint32_t*)(X2 + o1) : 0u;
            a2[2] = v0 ? *(const uint32_t*)(X2 + o0 + 16) : 0u;
            a2[3] = v1 ? *(const uint32_t*)(X2 + o1 + 16) : 0u;

            #pragma unroll
            for (int nt = 0; nt < 16; nt++) {
                int n = nt * 8 + gid;
                size_t boff = ((size_t)n * KPAD + k0) * 2;
                uint32_t b0 = *(const uint32_t*)(mw0 + boff);
                uint32_t b1 = *(const uint32_t*)(mw0 + boff + 16);
                mma_f16(cacc[nt], ahi, b0, b1);
                mma_f16(cacc[nt], alo, b0, b1);
                b0 = *(const uint32_t*)(mw1 + boff);
                b1 = *(const uint32_t*)(mw1 + boff + 16);
                mma_f16(cacc[nt], a1, b0, b1);
                b0 = *(const uint32_t*)(mw2 + boff);
                b1 = *(const uint32_t*)(mw2 + boff + 16);
                mma_f16(cacc[nt], a2, b0, b1);
            }
        }

        #pragma unroll
        for (int h = 0; h < 2; h++) {
            int r = r0 + h * 8;
            float s1 = 0.f, s2 = 0.f;
            #pragma unroll
            for (int nt = 0; nt < 16; nt++) {
                int col = nt * 8 + tig * 2;
                float a = cacc[nt][2 * h + 0] + sBias[col];
                float b = cacc[nt][2 * h + 1] + sBias[col + 1];
                cacc[nt][2 * h + 0] = a;
                cacc[nt][2 * h + 1] = b;
                s1 += a + b;
                s2 += a * a + b * b;
            }
            s1 += __shfl_xor_sync(0xffffffffu, s1, 1);
            s2 += __shfl_xor_sync(0xffffffffu, s2, 1);
            s1 += __shfl_xor_sync(0xffffffffu, s1, 2);
            s2 += __shfl_xor_sync(0xffffffffu, s2, 2);
            float mean = s1 * (1.f / 128.f);
            float var  = s2 * (1.f / 128.f) - mean * mean;
            float inv  = rsqrtf(var + LN_EPS);
            if (r < NN) {
                #pragma unroll
                for (int nt = 0; nt < 16; nt++) {
                    int col = nt * 8 + tig * 2;
                    float2 o;
                    o.x = fmaxf((cacc[nt][2 * h] - mean) * inv * sGamma[col]
                                + sBeta[col], 0.f);
                    o.y = fmaxf((cacc[nt][2 * h + 1] - mean) * inv * sGamma[col + 1]
                                + sBeta[col + 1], 0.f);
                    *(float2*)(out + (size_t)r * 128 + col) = o;
                }
            }
        }
        __syncthreads();
    }
}

// ================= launch =================
extern "C" void kernel_launch(void* const* d_in, const int* in_sizes, int n_in,
                              void* d_out, int out_size) {
    const float* x     = (const float*)d_in[0];
    const float* ew    = (const float*)d_in[1];
    const float* W     = (const float*)d_in[2];
    const float* bias  = (const float*)d_in[3];
    const float* gamma = (const float*)d_in[4];
    const float* beta  = (const float*)d_in[5];
    const int*   ei    = (const int*)d_in[6];
    float* out = (float*)d_out;

    uint2 *Xh, *T1h, *T2h;
    cudaGetSymbolAddress((void**)&Xh, g_xh);
    cudaGetSymbolAddress((void**)&T1h, g_t1h);
    cudaGetSymbolAddress((void**)&T2h, g_t2h);

    cudaFuncSetAttribute(gemm_mma_kernel,
                         cudaFuncAttributeMaxDynamicSharedMemorySize,
                         GEMM_SMEM);

    convert_degree_kernel<<<(NN * 32 + 255) / 256, 256>>>(x, ei, ew);
    scan_reduce_kernel<<<SCAN_BLKS, 256>>>();
    scan_apply_kernel<<<SCAN_BLKS, 256>>>();
    scatter_kernel<<<(EE + 255) / 256, 256>>>(ei, ew);

    spmm_kernel<<<(NN * 32 + 255) / 256, 256>>>(Xh, T1h, nullptr, 1.0f);
    spmm_kernel<<<(NN * 32 + 255) / 256, 256>>>(T1h, T2h, Xh, 2.0f);

    gemm_mma_kernel<<<296, 256, GEMM_SMEM>>>(x, (const char*)T1h,
                                             (const char*)T2h,
                                             W, bias, gamma, beta, out);
}

// round 10
// speedup vs baseline: 1.1058x; 1.1058x over previous
#include <cuda_runtime.h>
#include <cuda_bf16.h>
#include <cuda_fp16.h>
#include <cstdint>

#define NN 40000
#define EE 640000
#define DD 128
#define LN_EPS 1e-5f
#define SCAN_BLKS 157   // ceil(40000/256)

// ================= device scratch =================
__device__ unsigned long long g_deg[NN];          // packed cnt<<44 | fx24
__device__ __align__(16) float g_dinv[NN];
__device__ int   g_rowptr[NN + 1];
__device__ int   g_cursor[NN];
__device__ int   g_part[SCAN_BLKS];
__device__ __align__(16) uint2 g_cv[EE];          // packed {col, val bits}
__device__ __align__(16) uint2 g_xh[(size_t)NN * 32];   // x fp16
__device__ __align__(16) uint2 g_t1h[(size_t)NN * 32];  // T1 fp16
__device__ __align__(16) uint2 g_t2h[(size_t)NN * 32];  // T2 fp16
__device__ int   g_tile_ctr;

// ================= K1: fused convert(x->fp16) + degree =================
// Non-returning atomic -> REDG path (no scoreboard stall).
__global__ void convert_degree_kernel(const float* __restrict__ x,
                                      const int* __restrict__ ei,
                                      const float* __restrict__ w) {
    int i = blockIdx.x * blockDim.x + threadIdx.x;
    if (i < NN * 32) {
        float4 v = ((const float4*)x)[i];
        __half2 a = __floats2half2_rn(v.x, v.y);
        __half2 b = __floats2half2_rn(v.z, v.w);
        uint2 u;
        u.x = *reinterpret_cast<uint32_t*>(&a);
        u.y = *reinterpret_cast<uint32_t*>(&b);
        g_xh[i] = u;
    }
    if (i < EE) {
        int r = ei[i];
        if ((unsigned)r < NN) {
            unsigned long long fx =
                (unsigned long long)(w[i] * 16777216.0f);   // w * 2^24
            atomicAdd(&g_deg[r], (1ull << 44) | fx);
        }
    }
}

// ================= K2a: per-block count sums =================
__global__ void scan_reduce_kernel() {
    int i = blockIdx.x * 256 + threadIdx.x;
    int v = (i < NN) ? (int)(g_deg[i] >> 44) : 0;
    #pragma unroll
    for (int o = 16; o; o >>= 1) v += __shfl_xor_sync(0xffffffffu, v, o);
    __shared__ int ws[8];
    if ((threadIdx.x & 31) == 0) ws[threadIdx.x >> 5] = v;
    __syncthreads();
    if (threadIdx.x == 0) {
        int s = 0;
        #pragma unroll
        for (int k = 0; k < 8; k++) s += ws[k];
        g_part[blockIdx.x] = s;
    }
}

// ===== K2b: apply scan (each block scans partials locally), dinv, reset ====
__global__ void scan_apply_kernel() {
    __shared__ int pbuf[SCAN_BLKS];
    __shared__ int s_base;
    __shared__ int ws[8];
    int tid = threadIdx.x;
    if (tid < SCAN_BLKS) pbuf[tid] = g_part[tid];
    __syncthreads();
    if (tid == 0) {
        int run = 0;
        #pragma unroll 1
        for (int k = 0; k < SCAN_BLKS; k++) {
            int t = pbuf[k];
            if (k == blockIdx.x) { s_base = run; break; }
            run += t;
        }
    }

    int i = blockIdx.x * 256 + tid;
    int lane = tid & 31, wid = tid >> 5;
    unsigned long long pk = (i < NN) ? g_deg[i] : 0ull;
    int v = (int)(pk >> 44);
    int s = v;
    #pragma unroll
    for (int o = 1; o < 32; o <<= 1) {
        int t = __shfl_up_sync(0xffffffffu, s, o);
        if (lane >= o) s += t;
    }
    if (lane == 31) ws[wid] = s;
    __syncthreads();
    if (wid == 0 && lane < 8) {
        int t = ws[lane];
        #pragma unroll
        for (int o = 1; o < 8; o <<= 1) {
            int u = __shfl_up_sync(0xffu, t, o);
            if (lane >= o) t += u;
        }
        ws[lane] = t;
    }
    __syncthreads();
    int excl = s - v + (wid ? ws[wid - 1] : 0) + s_base;
    if (i < NN) {
        g_rowptr[i] = excl;
        g_cursor[i] = excl;
        float dg = (float)(pk & ((1ull << 44) - 1)) * 5.9604644775390625e-8f;
        g_dinv[i] = (dg > 0.f) ? rsqrtf(dg) : 0.f;
        g_deg[i] = 0ull;            // ready for next replay
    }
    if (i == 0) {
        g_tile_ctr = 0;
        g_rowptr[NN] = EE;
    }
}

// ================= K3: scatter (cursor atomics) =================
__global__ void scatter_kernel(const int* __restrict__ ei,
                               const float* __restrict__ w) {
    int e = blockIdx.x * blockDim.x + threadIdx.x;
    if (e >= EE) return;
    int r = ei[e];
    int c = ei[EE + e];
    if ((unsigned)r >= NN || (unsigned)c >= NN) return;
    int pos = atomicAdd(&g_cursor[r], 1);
    float val = -g_dinv[r] * w[e] * g_dinv[c];
    uint2 cv;
    cv.x = (uint32_t)c;
    cv.y = __float_as_uint(val);
    g_cv[pos] = cv;
}

// ================= K4/K5: SpMM fp16 in / fp16 out (unroll 2) ===============
__global__ void spmm_kernel(const uint2* __restrict__ Xh,
                            uint2* __restrict__ Yh,
                            const uint2* __restrict__ XsubH,
                            float alpha) {
    int gw = (blockIdx.x * blockDim.x + threadIdx.x) >> 5;
    if (gw >= NN) return;
    int lane = threadIdx.x & 31;
    int s = g_rowptr[gw], e2 = g_rowptr[gw + 1];
    float4 acc = make_float4(0.f, 0.f, 0.f, 0.f);
    int j = s;
    for (; j + 1 < e2; j += 2) {
        uint2 cv0 = g_cv[j], cv1 = g_cv[j + 1];
        uint2 h0 = Xh[(size_t)cv0.x * 32 + lane];
        uint2 h1 = Xh[(size_t)cv1.x * 32 + lane];
        float v0 = __uint_as_float(cv0.y), v1 = __uint_as_float(cv1.y);
        float2 a0 = __half22float2(*reinterpret_cast<__half2*>(&h0.x));
        float2 b0 = __half22float2(*reinterpret_cast<__half2*>(&h0.y));
        float2 a1 = __half22float2(*reinterpret_cast<__half2*>(&h1.x));
        float2 b1 = __half22float2(*reinterpret_cast<__half2*>(&h1.y));
        acc.x += v0 * a0.x; acc.y += v0 * a0.y; acc.z += v0 * b0.x; acc.w += v0 * b0.y;
        acc.x += v1 * a1.x; acc.y += v1 * a1.y; acc.z += v1 * b1.x; acc.w += v1 * b1.y;
    }
    if (j < e2) {
        uint2 cv0 = g_cv[j];
        uint2 h0 = Xh[(size_t)cv0.x * 32 + lane];
        float v0 = __uint_as_float(cv0.y);
        float2 a0 = __half22float2(*reinterpret_cast<__half2*>(&h0.x));
        float2 b0 = __half22float2(*reinterpret_cast<__half2*>(&h0.y));
        acc.x += v0 * a0.x; acc.y += v0 * a0.y; acc.z += v0 * b0.x; acc.w += v0 * b0.y;
    }
    float4 o;
    if (XsubH) {
        uint2 xs = XsubH[(size_t)gw * 32 + lane];
        float2 xa = __half22float2(*reinterpret_cast<__half2*>(&xs.x));
        float2 xb = __half22float2(*reinterpret_cast<__half2*>(&xs.y));
        o.x = alpha * acc.x - xa.x;
        o.y = alpha * acc.y - xa.y;
        o.z = alpha * acc.z - xb.x;
        o.w = alpha * acc.w - xb.y;
    } else {
        o.x = alpha * acc.x; o.y = alpha * acc.y;
        o.z = alpha * acc.z; o.w = alpha * acc.w;
    }
    __half2 ha = __floats2half2_rn(o.x, o.y);
    __half2 hb = __floats2half2_rn(o.z, o.w);
    uint2 u;
    u.x = *reinterpret_cast<uint32_t*>(&ha);
    u.y = *reinterpret_cast<uint32_t*>(&hb);
    Yh[(size_t)gw * 32 + lane] = u;
}

// ================= K6: fp16 mma GEMM + bias + LN + ReLU =================
#define NT 313
#define KPAD 136
#define MAT_BYTES (128 * KPAD * 2)
#define OFF_BIAS  (3 * MAT_BYTES)
#define OFF_GAMMA (OFF_BIAS + 512)
#define OFF_BETA  (OFF_GAMMA + 512)
#define GEMM_SMEM (OFF_BETA + 512)      // 105984 (x2 CTAs)

__device__ __forceinline__ void mma_f16(float* c, const uint32_t* a,
                                        uint32_t b0, uint32_t b1) {
    asm volatile(
        "mma.sync.aligned.m16n8k16.row.col.f32.f16.f16.f32 "
        "{%0,%1,%2,%3}, {%4,%5,%6,%7}, {%8,%9}, {%0,%1,%2,%3};"
        : "+f"(c[0]), "+f"(c[1]), "+f"(c[2]), "+f"(c[3])
        : "r"(a[0]), "r"(a[1]), "r"(a[2]), "r"(a[3]), "r"(b0), "r"(b1));
}

__device__ __forceinline__ void split2h(float x, float y,
                                        uint32_t& hi, uint32_t& lo) {
    __half hx = __float2half_rn(x);
    __half hy = __float2half_rn(y);
    float lx = x - __half2float(hx);
    float ly = y - __half2float(hy);
    __half2 h = __halves2half2(hx, hy);
    __half2 l = __halves2half2(__float2half_rn(lx), __float2half_rn(ly));
    hi = *reinterpret_cast<uint32_t*>(&h);
    lo = *reinterpret_cast<uint32_t*>(&l);
}

__global__ __launch_bounds__(256, 2)
void gemm_mma_kernel(const float* __restrict__ X0,
                     const char* __restrict__ X1,     // fp16 rows, 256B/row
                     const char* __restrict__ X2,     // fp16 rows
                     const float* __restrict__ W,
                     const float* __restrict__ bias,
                     const float* __restrict__ gamma,
                     const float* __restrict__ beta,
                     float* __restrict__ out) {
    extern __shared__ char smem[];
    __shared__ int s_tile;
    int tid = threadIdx.x;
    int wid = tid >> 5, lane = tid & 31;
    int tig = lane & 3, gid = lane >> 2;

    float* sBias  = (float*)(smem + OFF_BIAS);
    float* sGamma = (float*)(smem + OFF_GAMMA);
    float* sBeta  = (float*)(smem + OFF_BETA);
    if (tid < 128) {
        sBias[tid]  = bias[tid];
        sGamma[tid] = gamma[tid];
        sBeta[tid]  = beta[tid];
    }

    for (int idx = tid; idx < 3 * 16384; idx += 256) {
        int p = idx >> 14;
        int r = idx & 16383;
        int k = r >> 7, n = r & 127;
        *(__half*)(smem + p * MAT_BYTES + ((size_t)n * KPAD + k) * 2) =
            __float2half_rn(W[idx]);
    }
    __syncthreads();

    for (;;) {
        if (tid == 0) s_tile = atomicAdd(&g_tile_ctr, 1);
        __syncthreads();
        int tile = s_tile;
        if (tile >= NT) break;
        int row0 = tile * 128;

        int r0 = row0 + wid * 16 + gid;
        bool v0 = r0 < NN, v1 = (r0 + 8) < NN;

        float cacc[16][4];
        #pragma unroll
        for (int nt = 0; nt < 16; nt++)
            #pragma unroll
            for (int j = 0; j < 4; j++) cacc[nt][j] = 0.f;

        const char* mw0 = smem;
        const char* mw1 = smem + MAT_BYTES;
        const char* mw2 = smem + 2 * MAT_BYTES;

        #pragma unroll 1
        for (int ks = 0; ks < 8; ks++) {
            int k0 = ks * 16 + tig * 2;
            float2 z = make_float2(0.f, 0.f);
            float2 a00 = v0 ? *(const float2*)(X0 + (size_t)r0 * 128 + k0) : z;
            float2 a10 = v1 ? *(const float2*)(X0 + (size_t)(r0 + 8) * 128 + k0) : z;
            float2 a01 = v0 ? *(const float2*)(X0 + (size_t)r0 * 128 + k0 + 8) : z;
            float2 a11 = v1 ? *(const float2*)(X0 + (size_t)(r0 + 8) * 128 + k0 + 8) : z;
            uint32_t ahi[4], alo[4];
            split2h(a00.x, a00.y, ahi[0], alo[0]);
            split2h(a10.x, a10.y, ahi[1], alo[1]);
            split2h(a01.x, a01.y, ahi[2], alo[2]);
            split2h(a11.x, a11.y, ahi[3], alo[3]);
            uint32_t a1[4], a2[4];
            size_t o0 = (size_t)r0 * 256 + k0 * 2;
            size_t o1 = (size_t)(r0 + 8) * 256 + k0 * 2;
            a1[0] = v0 ? *(const uint32_t*)(X1 + o0) : 0u;
            a1[1] = v1 ? *(const uint32_t*)(X1 + o1) : 0u;
            a1[2] = v0 ? *(const uint32_t*)(X1 + o0 + 16) : 0u;
            a1[3] = v1 ? *(const uint32_t*)(X1 + o1 + 16) : 0u;
            a2[0] = v0 ? *(const uint32_t*)(X2 + o0) : 0u;
            a2[1] = v1 ? *(const uint32_t*)(X2 + o1) : 0u;
            a2[2] = v0 ? *(const uint32_t*)(X2 + o0 + 16) : 0u;
            a2[3] = v1 ? *(const uint32_t*)(X2 + o1 + 16) : 0u;

            #pragma unroll
            for (int nt = 0; nt < 16; nt++) {
                int n = nt * 8 + gid;
                size_t boff = ((size_t)n * KPAD + k0) * 2;
                uint32_t b0 = *(const uint32_t*)(mw0 + boff);
                uint32_t b1 = *(const uint32_t*)(mw0 + boff + 16);
                mma_f16(cacc[nt], ahi, b0, b1);
                mma_f16(cacc[nt], alo, b0, b1);
                b0 = *(const uint32_t*)(mw1 + boff);
                b1 = *(const uint32_t*)(mw1 + boff + 16);
                mma_f16(cacc[nt], a1, b0, b1);
                b0 = *(const uint32_t*)(mw2 + boff);
                b1 = *(const uint32_t*)(mw2 + boff + 16);
                mma_f16(cacc[nt], a2, b0, b1);
            }
        }

        #pragma unroll
        for (int h = 0; h < 2; h++) {
            int r = r0 + h * 8;
            float s1 = 0.f, s2 = 0.f;
            #pragma unroll
            for (int nt = 0; nt < 16; nt++) {
                int col = nt * 8 + tig * 2;
                float a = cacc[nt][2 * h + 0] + sBias[col];
                float b = cacc[nt][2 * h + 1] + sBias[col + 1];
                cacc[nt][2 * h + 0] = a;
                cacc[nt][2 * h + 1] = b;
                s1 += a + b;
                s2 += a * a + b * b;
            }
            s1 += __shfl_xor_sync(0xffffffffu, s1, 1);
            s2 += __shfl_xor_sync(0xffffffffu, s2, 1);
            s1 += __shfl_xor_sync(0xffffffffu, s1, 2);
            s2 += __shfl_xor_sync(0xffffffffu, s2, 2);
            float mean = s1 * (1.f / 128.f);
            float var  = s2 * (1.f / 128.f) - mean * mean;
            float inv  = rsqrtf(var + LN_EPS);
            if (r < NN) {
                #pragma unroll
                for (int nt = 0; nt < 16; nt++) {
                    int col = nt * 8 + tig * 2;
                    float2 o;
                    o.x = fmaxf((cacc[nt][2 * h] - mean) * inv * sGamma[col]
                                + sBeta[col], 0.f);
                    o.y = fmaxf((cacc[nt][2 * h + 1] - mean) * inv * sGamma[col + 1]
                                + sBeta[col + 1], 0.f);
                    *(float2*)(out + (size_t)r * 128 + col) = o;
                }
            }
        }
        __syncthreads();
    }
}

// ================= launch =================
extern "C" void kernel_launch(void* const* d_in, const int* in_sizes, int n_in,
                              void* d_out, int out_size) {
    const float* x     = (const float*)d_in[0];
    const float* ew    = (const float*)d_in[1];
    const float* W     = (const float*)d_in[2];
    const float* bias  = (const float*)d_in[3];
    const float* gamma = (const float*)d_in[4];
    const float* beta  = (const float*)d_in[5];
    const int*   ei    = (const int*)d_in[6];
    float* out = (float*)d_out;

    uint2 *Xh, *T1h, *T2h;
    cudaGetSymbolAddress((void**)&Xh, g_xh);
    cudaGetSymbolAddress((void**)&T1h, g_t1h);
    cudaGetSymbolAddress((void**)&T2h, g_t2h);

    cudaFuncSetAttribute(gemm_mma_kernel,
                         cudaFuncAttributeMaxDynamicSharedMemorySize,
                         GEMM_SMEM);

    convert_degree_kernel<<<(NN * 32 + 255) / 256, 256>>>(x, ei, ew);
    scan_reduce_kernel<<<SCAN_BLKS, 256>>>();
    scan_apply_kernel<<<SCAN_BLKS, 256>>>();
    scatter_kernel<<<(EE + 255) / 256, 256>>>(ei, ew);

    spmm_kernel<<<(NN * 32 + 255) / 256, 256>>>(Xh, T1h, nullptr, 1.0f);
    spmm_kernel<<<(NN * 32 + 255) / 256, 256>>>(T1h, T2h, Xh, 2.0f);

    gemm_mma_kernel<<<296, 256, GEMM_SMEM>>>(x, (const char*)T1h,
                                             (const char*)T2h,
                                             W, bias, gamma, beta, out);
}

// round 11
// speedup vs baseline: 1.2197x; 1.1030x over previous
#include <cuda_runtime.h>
#include <cuda_bf16.h>
#include <cuda_fp16.h>
#include <cstdint>

#define NN 40000
#define EE 640000
#define DD 128
#define LN_EPS 1e-5f
#define SCAN_BLKS 157   // ceil(40000/256)
#define KPAD 136
#define WH_ELEMS (3 * 128 * KPAD)

// ================= device scratch =================
__device__ unsigned long long g_deg[NN];          // packed cnt<<44 | fx24
__device__ __align__(16) float g_dinv[NN];
__device__ int   g_rowptr[NN + 1];
__device__ int   g_cursor[NN];
__device__ int   g_part[SCAN_BLKS];
__device__ __align__(16) uint2 g_cv[EE];          // packed {col, val bits}
__device__ __align__(16) uint2 g_xh[(size_t)NN * 32];   // x fp16
__device__ __align__(16) uint2 g_t1h[(size_t)NN * 32];  // T1 fp16
__device__ __align__(16) uint2 g_t2h[(size_t)NN * 32];  // T2 fp16
__device__ __align__(16) __half g_wh[WH_ELEMS];   // W fp16, [p][n][KPAD]
__device__ int   g_tile_ctr;

// ========= K1: fused convert(x->fp16) + W->fp16 transpose + degree =========
__global__ void convert_degree_kernel(const float* __restrict__ x,
                                      const float* __restrict__ W,
                                      const int* __restrict__ ei,
                                      const float* __restrict__ w) {
    int i = blockIdx.x * blockDim.x + threadIdx.x;
    if (i < NN * 32) {
        float4 v = ((const float4*)x)[i];
        __half2 a = __floats2half2_rn(v.x, v.y);
        __half2 b = __floats2half2_rn(v.z, v.w);
        uint2 u;
        u.x = *reinterpret_cast<uint32_t*>(&a);
        u.y = *reinterpret_cast<uint32_t*>(&b);
        g_xh[i] = u;
    }
    if (i < 3 * 16384) {             // W: [p][k][n] -> g_wh [p][n][KPAD]
        int p = i >> 14;
        int r = i & 16383;
        int k = r >> 7, n = r & 127;
        g_wh[p * 128 * KPAD + n * KPAD + k] = __float2half_rn(W[i]);
    }
    if (i < EE) {
        int r = ei[i];
        if ((unsigned)r < NN) {
            unsigned long long fx =
                (unsigned long long)(w[i] * 16777216.0f);   // w * 2^24
            atomicAdd(&g_deg[r], (1ull << 44) | fx);         // non-returning
        }
    }
}

// ================= K2a: per-block count sums =================
__global__ void scan_reduce_kernel() {
    int i = blockIdx.x * 256 + threadIdx.x;
    int v = (i < NN) ? (int)(g_deg[i] >> 44) : 0;
    #pragma unroll
    for (int o = 16; o; o >>= 1) v += __shfl_xor_sync(0xffffffffu, v, o);
    __shared__ int ws[8];
    if ((threadIdx.x & 31) == 0) ws[threadIdx.x >> 5] = v;
    __syncthreads();
    if (threadIdx.x == 0) {
        int s = 0;
        #pragma unroll
        for (int k = 0; k < 8; k++) s += ws[k];
        g_part[blockIdx.x] = s;
    }
}

// == K2b: apply scan (parallel block-scan of partials), dinv, reset ========
__global__ void scan_apply_kernel() {
    __shared__ int pex[SCAN_BLKS];
    __shared__ int ws2[8];
    __shared__ int ws[8];
    int tid = threadIdx.x;
    int lane = tid & 31, wid = tid >> 5;

    // --- parallel exclusive scan of the 157 partials ---
    int pv = (tid < SCAN_BLKS) ? g_part[tid] : 0;
    int ps = pv;
    #pragma unroll
    for (int o = 1; o < 32; o <<= 1) {
        int t = __shfl_up_sync(0xffffffffu, ps, o);
        if (lane >= o) ps += t;
    }
    if (lane == 31) ws2[wid] = ps;
    __syncthreads();
    if (wid == 0 && lane < 8) {
        int t = ws2[lane];
        #pragma unroll
        for (int o = 1; o < 8; o <<= 1) {
            int u = __shfl_up_sync(0xffu, t, o);
            if (lane >= o) t += u;
        }
        ws2[lane] = t;
    }
    __syncthreads();
    if (tid < SCAN_BLKS)
        pex[tid] = ps - pv + (wid ? ws2[wid - 1] : 0);
    __syncthreads();
    int s_base = pex[blockIdx.x];

    // --- per-element scan within this block's 256 nodes ---
    int i = blockIdx.x * 256 + tid;
    unsigned long long pk = (i < NN) ? g_deg[i] : 0ull;
    int v = (int)(pk >> 44);
    int s = v;
    #pragma unroll
    for (int o = 1; o < 32; o <<= 1) {
        int t = __shfl_up_sync(0xffffffffu, s, o);
        if (lane >= o) s += t;
    }
    if (lane == 31) ws[wid] = s;
    __syncthreads();
    if (wid == 0 && lane < 8) {
        int t = ws[lane];
        #pragma unroll
        for (int o = 1; o < 8; o <<= 1) {
            int u = __shfl_up_sync(0xffu, t, o);
            if (lane >= o) t += u;
        }
        ws[lane] = t;
    }
    __syncthreads();
    int excl = s - v + (wid ? ws[wid - 1] : 0) + s_base;
    if (i < NN) {
        g_rowptr[i] = excl;
        g_cursor[i] = excl;
        float dg = (float)(pk & ((1ull << 44) - 1)) * 5.9604644775390625e-8f;
        g_dinv[i] = (dg > 0.f) ? rsqrtf(dg) : 0.f;
        g_deg[i] = 0ull;            // ready for next replay
    }
    if (i == 0) {
        g_tile_ctr = 0;
        g_rowptr[NN] = EE;
    }
}

// ============ K3: scatter, 2 edges/thread (cursor atomics, MLP 2) ==========
__global__ void scatter_kernel(const int* __restrict__ ei,
                               const float* __restrict__ w) {
    int t = blockIdx.x * blockDim.x + threadIdx.x;
    int e = t * 2;
    if (e >= EE) return;
    int2   rr = *(const int2*)(ei + e);
    int2   cc = *(const int2*)(ei + EE + e);
    float2 ww = *(const float2*)(w + e);
    bool ok0 = (unsigned)rr.x < NN && (unsigned)cc.x < NN;
    bool ok1 = (unsigned)rr.y < NN && (unsigned)cc.y < NN;
    float val0 = ok0 ? -g_dinv[rr.x] * ww.x * g_dinv[cc.x] : 0.f;
    float val1 = ok1 ? -g_dinv[rr.y] * ww.y * g_dinv[cc.y] : 0.f;
    int pos0 = ok0 ? atomicAdd(&g_cursor[rr.x], 1) : 0;
    int pos1 = ok1 ? atomicAdd(&g_cursor[rr.y], 1) : 0;
    if (ok0) {
        uint2 cv; cv.x = (uint32_t)cc.x; cv.y = __float_as_uint(val0);
        g_cv[pos0] = cv;
    }
    if (ok1) {
        uint2 cv; cv.x = (uint32_t)cc.y; cv.y = __float_as_uint(val1);
        g_cv[pos1] = cv;
    }
}

// ================= K4/K5: SpMM fp16 in / fp16 out (unroll 2) ===============
__global__ void spmm_kernel(const uint2* __restrict__ Xh,
                            uint2* __restrict__ Yh,
                            const uint2* __restrict__ XsubH,
                            float alpha) {
    int gw = (blockIdx.x * blockDim.x + threadIdx.x) >> 5;
    if (gw >= NN) return;
    int lane = threadIdx.x & 31;
    int s = g_rowptr[gw], e2 = g_rowptr[gw + 1];
    float4 acc = make_float4(0.f, 0.f, 0.f, 0.f);
    int j = s;
    for (; j + 1 < e2; j += 2) {
        uint2 cv0 = g_cv[j], cv1 = g_cv[j + 1];
        uint2 h0 = Xh[(size_t)cv0.x * 32 + lane];
        uint2 h1 = Xh[(size_t)cv1.x * 32 + lane];
        float v0 = __uint_as_float(cv0.y), v1 = __uint_as_float(cv1.y);
        float2 a0 = __half22float2(*reinterpret_cast<__half2*>(&h0.x));
        float2 b0 = __half22float2(*reinterpret_cast<__half2*>(&h0.y));
        float2 a1 = __half22float2(*reinterpret_cast<__half2*>(&h1.x));
        float2 b1 = __half22float2(*reinterpret_cast<__half2*>(&h1.y));
        acc.x += v0 * a0.x; acc.y += v0 * a0.y; acc.z += v0 * b0.x; acc.w += v0 * b0.y;
        acc.x += v1 * a1.x; acc.y += v1 * a1.y; acc.z += v1 * b1.x; acc.w += v1 * b1.y;
    }
    if (j < e2) {
        uint2 cv0 = g_cv[j];
        uint2 h0 = Xh[(size_t)cv0.x * 32 + lane];
        float v0 = __uint_as_float(cv0.y);
        float2 a0 = __half22float2(*reinterpret_cast<__half2*>(&h0.x));
        float2 b0 = __half22float2(*reinterpret_cast<__half2*>(&h0.y));
        acc.x += v0 * a0.x; acc.y += v0 * a0.y; acc.z += v0 * b0.x; acc.w += v0 * b0.y;
    }
    float4 o;
    if (XsubH) {
        uint2 xs = XsubH[(size_t)gw * 32 + lane];
        float2 xa = __half22float2(*reinterpret_cast<__half2*>(&xs.x));
        float2 xb = __half22float2(*reinterpret_cast<__half2*>(&xs.y));
        o.x = alpha * acc.x - xa.x;
        o.y = alpha * acc.y - xa.y;
        o.z = alpha * acc.z - xb.x;
        o.w = alpha * acc.w - xb.y;
    } else {
        o.x = alpha * acc.x; o.y = alpha * acc.y;
        o.z = alpha * acc.z; o.w = alpha * acc.w;
    }
    __half2 ha = __floats2half2_rn(o.x, o.y);
    __half2 hb = __floats2half2_rn(o.z, o.w);
    uint2 u;
    u.x = *reinterpret_cast<uint32_t*>(&ha);
    u.y = *reinterpret_cast<uint32_t*>(&hb);
    Yh[(size_t)gw * 32 + lane] = u;
}

// ================= K6: fp16 mma GEMM + bias + LN + ReLU =================
#define NT 313
#define MAT_BYTES (128 * KPAD * 2)
#define OFF_BIAS  (3 * MAT_BYTES)
#define OFF_GAMMA (OFF_BIAS + 512)
#define OFF_BETA  (OFF_GAMMA + 512)
#define GEMM_SMEM (OFF_BETA + 512)      // 105984 (x2 CTAs)

__device__ __forceinline__ void mma_f16(float* c, const uint32_t* a,
                                        uint32_t b0, uint32_t b1) {
    asm volatile(
        "mma.sync.aligned.m16n8k16.row.col.f32.f16.f16.f32 "
        "{%0,%1,%2,%3}, {%4,%5,%6,%7}, {%8,%9}, {%0,%1,%2,%3};"
        : "+f"(c[0]), "+f"(c[1]), "+f"(c[2]), "+f"(c[3])
        : "r"(a[0]), "r"(a[1]), "r"(a[2]), "r"(a[3]), "r"(b0), "r"(b1));
}

__device__ __forceinline__ void split2h(float x, float y,
                                        uint32_t& hi, uint32_t& lo) {
    __half hx = __float2half_rn(x);
    __half hy = __float2half_rn(y);
    float lx = x - __half2float(hx);
    float ly = y - __half2float(hy);
    __half2 h = __halves2half2(hx, hy);
    __half2 l = __halves2half2(__float2half_rn(lx), __float2half_rn(ly));
    hi = *reinterpret_cast<uint32_t*>(&h);
    lo = *reinterpret_cast<uint32_t*>(&l);
}

__global__ __launch_bounds__(256, 2)
void gemm_mma_kernel(const float* __restrict__ X0,
                     const char* __restrict__ X1,     // fp16 rows, 256B/row
                     const char* __restrict__ X2,     // fp16 rows
                     const float* __restrict__ bias,
                     const float* __restrict__ gamma,
                     const float* __restrict__ beta,
                     float* __restrict__ out) {
    extern __shared__ char smem[];
    __shared__ int s_tile;
    int tid = threadIdx.x;
    int wid = tid >> 5, lane = tid & 31;
    int tig = lane & 3, gid = lane >> 2;

    float* sBias  = (float*)(smem + OFF_BIAS);
    float* sGamma = (float*)(smem + OFF_GAMMA);
    float* sBeta  = (float*)(smem + OFF_BETA);
    if (tid < 128) {
        sBias[tid]  = bias[tid];
        sGamma[tid] = gamma[tid];
        sBeta[tid]  = beta[tid];
    }

    // stage pre-converted W: vector memcpy (6528 uint4)
    {
        const uint4* src = (const uint4*)g_wh;
        uint4* dst = (uint4*)smem;
        for (int idx = tid; idx < WH_ELEMS / 8; idx += 256)
            dst[idx] = src[idx];
    }
    __syncthreads();

    for (;;) {
        if (tid == 0) s_tile = atomicAdd(&g_tile_ctr, 1);
        __syncthreads();
        int tile = s_tile;
        if (tile >= NT) break;
        int row0 = tile * 128;

        int r0 = row0 + wid * 16 + gid;
        bool v0 = r0 < NN, v1 = (r0 + 8) < NN;

        float cacc[16][4];
        #pragma unroll
        for (int nt = 0; nt < 16; nt++)
            #pragma unroll
            for (int j = 0; j < 4; j++) cacc[nt][j] = 0.f;

        const char* mw0 = smem;
        const char* mw1 = smem + MAT_BYTES;
        const char* mw2 = smem + 2 * MAT_BYTES;

        #pragma unroll 1
        for (int ks = 0; ks < 8; ks++) {
            int k0 = ks * 16 + tig * 2;
            float2 z = make_float2(0.f, 0.f);
            float2 a00 = v0 ? *(const float2*)(X0 + (size_t)r0 * 128 + k0) : z;
            float2 a10 = v1 ? *(const float2*)(X0 + (size_t)(r0 + 8) * 128 + k0) : z;
            float2 a01 = v0 ? *(const float2*)(X0 + (size_t)r0 * 128 + k0 + 8) : z;
            float2 a11 = v1 ? *(const float2*)(X0 + (size_t)(r0 + 8) * 128 + k0 + 8) : z;
            uint32_t ahi[4], alo[4];
            split2h(a00.x, a00.y, ahi[0], alo[0]);
            split2h(a10.x, a10.y, ahi[1], alo[1]);
            split2h(a01.x, a01.y, ahi[2], alo[2]);
            split2h(a11.x, a11.y, ahi[3], alo[3]);
            uint32_t a1[4], a2[4];
            size_t o0 = (size_t)r0 * 256 + k0 * 2;
            size_t o1 = (size_t)(r0 + 8) * 256 + k0 * 2;
            a1[0] = v0 ? *(const uint32_t*)(X1 + o0) : 0u;
            a1[1] = v1 ? *(const uint32_t*)(X1 + o1) : 0u;
            a1[2] = v0 ? *(const uint32_t*)(X1 + o0 + 16) : 0u;
            a1[3] = v1 ? *(const uint32_t*)(X1 + o1 + 16) : 0u;
            a2[0] = v0 ? *(const uint32_t*)(X2 + o0) : 0u;
            a2[1] = v1 ? *(const uint32_t*)(X2 + o1) : 0u;
            a2[2] = v0 ? *(const uint32_t*)(X2 + o0 + 16) : 0u;
            a2[3] = v1 ? *(const uint32_t*)(X2 + o1 + 16) : 0u;

            #pragma unroll
            for (int nt = 0; nt < 16; nt++) {
                int n = nt * 8 + gid;
                size_t boff = ((size_t)n * KPAD + k0) * 2;
                uint32_t b0 = *(const uint32_t*)(mw0 + boff);
                uint32_t b1 = *(const uint32_t*)(mw0 + boff + 16);
                mma_f16(cacc[nt], ahi, b0, b1);
                mma_f16(cacc[nt], alo, b0, b1);
                b0 = *(const uint32_t*)(mw1 + boff);
                b1 = *(const uint32_t*)(mw1 + boff + 16);
                mma_f16(cacc[nt], a1, b0, b1);
                b0 = *(const uint32_t*)(mw2 + boff);
                b1 = *(const uint32_t*)(mw2 + boff + 16);
                mma_f16(cacc[nt], a2, b0, b1);
            }
        }

        #pragma unroll
        for (int h = 0; h < 2; h++) {
            int r = r0 + h * 8;
            float s1 = 0.f, s2 = 0.f;
            #pragma unroll
            for (int nt = 0; nt < 16; nt++) {
                int col = nt * 8 + tig * 2;
                float a = cacc[nt][2 * h + 0] + sBias[col];
                float b = cacc[nt][2 * h + 1] + sBias[col + 1];
                cacc[nt][2 * h + 0] = a;
                cacc[nt][2 * h + 1] = b;
                s1 += a + b;
                s2 += a * a + b * b;
            }
            s1 += __shfl_xor_sync(0xffffffffu, s1, 1);
            s2 += __shfl_xor_sync(0xffffffffu, s2, 1);
            s1 += __shfl_xor_sync(0xffffffffu, s1, 2);
            s2 += __shfl_xor_sync(0xffffffffu, s2, 2);
            float mean = s1 * (1.f / 128.f);
            float var  = s2 * (1.f / 128.f) - mean * mean;
            float inv  = rsqrtf(var + LN_EPS);
            if (r < NN) {
                #pragma unroll
                for (int nt = 0; nt < 16; nt++) {
                    int col = nt * 8 + tig * 2;
                    float2 o;
                    o.x = fmaxf((cacc[nt][2 * h] - mean) * inv * sGamma[col]
                                + sBeta[col], 0.f);
                    o.y = fmaxf((cacc[nt][2 * h + 1] - mean) * inv * sGamma[col + 1]
                                + sBeta[col + 1], 0.f);
                    *(float2*)(out + (size_t)r * 128 + col) = o;
                }
            }
        }
        __syncthreads();
    }
}

// ================= launch =================
extern "C" void kernel_launch(void* const* d_in, const int* in_sizes, int n_in,
                              void* d_out, int out_size) {
    const float* x     = (const float*)d_in[0];
    const float* ew    = (const float*)d_in[1];
    const float* W     = (const float*)d_in[2];
    const float* bias  = (const float*)d_in[3];
    const float* gamma = (const float*)d_in[4];
    const float* beta  = (const float*)d_in[5];
    const int*   ei    = (const int*)d_in[6];
    float* out = (float*)d_out;

    uint2 *Xh, *T1h, *T2h;
    cudaGetSymbolAddress((void**)&Xh, g_xh);
    cudaGetSymbolAddress((void**)&T1h, g_t1h);
    cudaGetSymbolAddress((void**)&T2h, g_t2h);

    cudaFuncSetAttribute(gemm_mma_kernel,
                         cudaFuncAttributeMaxDynamicSharedMemorySize,
                         GEMM_SMEM);

    convert_degree_kernel<<<(NN * 32 + 255) / 256, 256>>>(x, W, ei, ew);
    scan_reduce_kernel<<<SCAN_BLKS, 256>>>();
    scan_apply_kernel<<<SCAN_BLKS, 256>>>();
    scatter_kernel<<<(EE / 2 + 255) / 256, 256>>>(ei, ew);

    spmm_kernel<<<(NN * 32 + 255) / 256, 256>>>(Xh, T1h, nullptr, 1.0f);
    spmm_kernel<<<(NN * 32 + 255) / 256, 256>>>(T1h, T2h, Xh, 2.0f);

    gemm_mma_kernel<<<296, 256, GEMM_SMEM>>>(x, (const char*)T1h,
                                             (const char*)T2h,
                                             bias, gamma, beta, out);
}